// round 15
// baseline (speedup 1.0000x reference)
#include <cuda_runtime.h>
#include <float.h>

// Problem constants
#define BB   64
#define DD   64
#define TTm  4096
#define KKm  512
#define TILE 128      // tokens per CTA
#define KCH  128      // codes per chunk
#define ESP  132      // padded smem stride for transposed emb chunk
#define NTH  256
#define NW   (NTH / 32)                  // 8 warps
#define GRID ((BB * TTm) / TILE)         // 2048

#define N_ELEM ((size_t)BB * DD * TTm)   // 16777216

// dynamic smem (floats): zs + es + c2s + x2s + kidx + rd + rk + wred
#define SMEM_FLOATS (DD*TILE + DD*ESP + KKm + TILE + TILE + NW*TILE + NW*TILE + NW)
#define SMEM_BYTES  (SMEM_FLOATS * 4)

__device__ double   g_loss;
__device__ unsigned g_done;     // zero-init; reset by last CTA each launch
__device__ float    g_c2[KKm];

// ---------------------------------------------------------------------------
// prep: codebook squared norms via 7-register stack fold == adjacent-pair
// balanced tree (reference numerics), spill-free, 8 blocks.
// ---------------------------------------------------------------------------
__global__ void vq_prep(const float* __restrict__ emb) {
    int k = blockIdx.x * 64 + threadIdx.x;    // grid 8 x 64 = 512 codes
    if (k == 0) g_loss = 0.0;
    const float* e = emb + k * DD;
    float st[7];
    int sp = 0;
    #pragma unroll
    for (int d = 0; d < DD; d++) {
        float v = e[d];
        float cur = __fmul_rn(v, v);
        int m = d;
        while (m & 1) { cur = __fadd_rn(st[--sp], cur); m >>= 1; }
        st[sp++] = cur;
    }
    g_c2[k] = st[0];
}

// ---------------------------------------------------------------------------
// main: fused distance GEMM. Warp = 128 tokens x 16 codes; thread = 4 tokens
// (lane*4..+3) x 16 codes. a-load: one conflict-free LDS.128; b-loads: 4
// broadcast LDS.128 -> ~8 smem wavefronts per 64 FFMA (FMA-pipe bound).
// Reference rounding: d = fl( fl(x2+c2) - fl(2*dot) ), ascending-d fma chain.
// ---------------------------------------------------------------------------
__global__ __launch_bounds__(NTH, 2)
void vq_main(const float* __restrict__ z, const float* __restrict__ emb,
             float* __restrict__ out) {
    extern __shared__ float smem[];
    float* zs   = smem;                       // 64*128
    float* es   = zs + DD * TILE;             // 64*132
    float* c2s  = es + DD * ESP;              // 512
    float* x2s  = c2s + KKm;                  // 128
    int*   kidx = (int*)(x2s + TILE);         // 128
    float* rd   = (float*)(kidx + TILE);      // 8*128
    int*   rk   = (int*)(rd + NW * TILE);     // 8*128
    float* wred = (float*)(rk + NW * TILE);   // 8

    const int tid  = threadIdx.x;
    const int wid  = tid >> 5, lane = tid & 31;
    const int tile = blockIdx.x;
    const int b    = tile >> 5;
    const int t0   = (tile & 31) * TILE;
    const size_t zbase = (size_t)b * DD * TTm + t0;

    // ---- load z tile [64 dims x 128 tokens] + full c2, coalesced ----
    for (int i = tid; i < DD * TILE / 4; i += NTH) {
        int row = i >> 5;
        int col = (i & 31) << 2;
        float4 v = *(const float4*)(z + zbase + (size_t)row * TTm + col);
        *(float4*)(zs + row * TILE + col) = v;
    }
    for (int i = tid; i < KKm; i += NTH) c2s[i] = g_c2[i];
    __syncthreads();

    // ---- per-token ||x||^2 (ascending-d fma chain; constant shift of all
    // 512 distances => argmin-order invariant) ----
    if (tid < TILE) {
        float s = 0.f;
        #pragma unroll
        for (int d = 0; d < DD; d++) {
            float v = zs[d * TILE + tid];
            s = fmaf(v, v, s);
        }
        x2s[tid] = s;
    }

    float bestd[4];
    int   bestk[4];
    #pragma unroll
    for (int i = 0; i < 4; i++) { bestd[i] = FLT_MAX; bestk[i] = 0; }

    #pragma unroll 1
    for (int c = 0; c < KKm / KCH; c++) {
        __syncthreads();   // prev chunk compute done; publishes x2s on c=0
        // load emb chunk transposed: es[d][kk] = emb[c*128+kk][d]
        for (int i = tid; i < KCH * DD / 4; i += NTH) {
            int kk = i >> 4;
            int dq = (i & 15) << 2;
            float4 v = *(const float4*)(emb + (size_t)(c * KCH + kk) * DD + dq);
            es[(dq + 0) * ESP + kk] = v.x;
            es[(dq + 1) * ESP + kk] = v.y;
            es[(dq + 2) * ESP + kk] = v.z;
            es[(dq + 3) * ESP + kk] = v.w;
        }
        __syncthreads();

        float acc[4][16];
        #pragma unroll
        for (int i = 0; i < 4; i++)
            #pragma unroll
            for (int j = 0; j < 16; j++) acc[i][j] = 0.f;

        // mainloop: 1 conflict-free a-LDS.128 + 4 broadcast b-LDS.128 + 64 FFMA
        #pragma unroll 2
        for (int d = 0; d < DD; d++) {
            float4 a  = *(const float4*)(zs + d * TILE + lane * 4);
            float4 b0 = *(const float4*)(es + d * ESP + wid * 16);
            float4 b1 = *(const float4*)(es + d * ESP + wid * 16 + 4);
            float4 b2 = *(const float4*)(es + d * ESP + wid * 16 + 8);
            float4 b3 = *(const float4*)(es + d * ESP + wid * 16 + 12);
            float av[4] = {a.x, a.y, a.z, a.w};
            float bv[16] = {b0.x, b0.y, b0.z, b0.w, b1.x, b1.y, b1.z, b1.w,
                            b2.x, b2.y, b2.z, b2.w, b3.x, b3.y, b3.z, b3.w};
            #pragma unroll
            for (int j = 0; j < 16; j++)
                #pragma unroll
                for (int i = 0; i < 4; i++)
                    acc[i][j] = fmaf(av[i], bv[j], acc[i][j]);
        }

        // chunk epilogue: d = fl( fl(x2+c2) - fl(2*dot) ), predicated argmin
        float x2r[4];
        #pragma unroll
        for (int i = 0; i < 4; i++) x2r[i] = x2s[lane * 4 + i];
        #pragma unroll
        for (int j = 0; j < 16; j++) {
            int   kg  = c * KCH + wid * 16 + j;
            float c2v = c2s[kg];
            #pragma unroll
            for (int i = 0; i < 4; i++) {
                float A  = __fadd_rn(x2r[i], c2v);
                float dv = __fsub_rn(A, __fmul_rn(2.0f, acc[i][j]));
                bool  lt = dv < bestd[i];
                bestd[i] = lt ? dv : bestd[i];
                bestk[i] = lt ? kg : bestk[i];
            }
        }
    }

    // ---- cross-warp argmin fold: each warp posts per-token candidates ----
    #pragma unroll
    for (int i = 0; i < 4; i++) {
        rd[wid * TILE + lane * 4 + i] = bestd[i];
        rk[wid * TILE + lane * 4 + i] = bestk[i];
    }
    __syncthreads();
    if (tid < TILE) {
        float bd = rd[tid];
        int   bk = rk[tid];
        #pragma unroll
        for (int w = 1; w < NW; w++) {
            float dv = rd[w * TILE + tid];
            int   kv = rk[w * TILE + tid];
            if (dv < bd || (dv == bd && kv < bk)) { bd = dv; bk = kv; }
        }
        kidx[tid] = bk;
    }
    __syncthreads();

    // ---- gather + straight-through output + loss (reference rounding) ----
    float lsum = 0.f;
    for (int i = tid; i < DD * TILE; i += NTH) {
        int d = i >> 7;
        int t = i & 127;
        float q  = __ldg(emb + kidx[t] * DD + d);
        float zv = zs[d * TILE + t];
        float diff = __fsub_rn(q, zv);
        out[zbase + (size_t)d * TTm + t] = __fadd_rn(zv, diff);
        lsum = fmaf(diff, diff, lsum);
    }
    #pragma unroll
    for (int o = 16; o > 0; o >>= 1)
        lsum += __shfl_down_sync(0xffffffffu, lsum, o);
    if (lane == 0) wred[wid] = lsum;
    __syncthreads();
    if (tid == 0) {
        float s = 0.f;
        #pragma unroll
        for (int w = 0; w < NW; w++) s += wred[w];
        atomicAdd(&g_loss, (double)s);
        // last CTA to finish writes the loss scalars and resets the counter
        __threadfence();
        unsigned n = atomicAdd(&g_done, 1u);
        if (n == GRID - 1) {
            double m = g_loss / (double)N_ELEM;
            out[N_ELEM]     = (float)m;           // vq_loss
            out[N_ELEM + 1] = (float)(0.25 * m);  // commitment
            g_done = 0;                           // ready for next replay
        }
    }
}

// ---------------------------------------------------------------------------
extern "C" void kernel_launch(void* const* d_in, const int* in_sizes, int n_in,
                              void* d_out, int out_size) {
    const float* z   = (const float*)d_in[0];
    const float* emb = (const float*)d_in[1];
    float*       out = (float*)d_out;

    (void)cudaFuncSetAttribute(vq_main,
                               cudaFuncAttributeMaxDynamicSharedMemorySize,
                               SMEM_BYTES);

    vq_prep<<<8, 64>>>(emb);
    vq_main<<<GRID, NTH, SMEM_BYTES>>>(z, emb, out);
}

// round 17
// speedup vs baseline: 1.4030x; 1.4030x over previous
#include <cuda_runtime.h>
#include <float.h>

// Problem constants
#define BB   64
#define DD   64
#define TTm  4096
#define KKm  512
#define TILE 128      // tokens per CTA
#define KCH  128      // codes per chunk
#define ESP  132      // padded smem stride for es (kept identical to r13)
#define NTH  256
#define NW   (NTH / 32)
#define GRID ((BB * TTm) / TILE)         // 2048

#define N_ELEM ((size_t)BB * DD * TTm)   // 16777216

// dynamic smem (floats): zs + 2x es + c2s + x2s + kidx + wred
#define SMEM_FLOATS (DD*TILE + 2*DD*ESP + KKm + TILE + TILE + NW)
#define SMEM_BYTES  (SMEM_FLOATS * 4)    // 103,456 B -> 2 CTAs/SM

__device__ double   g_loss;
__device__ unsigned g_done;              // zero-init; reset by last CTA
__device__ float    g_c2[KKm];
__device__ float    g_ebt[4 * DD * KCH]; // [chunk][d][kk] = 2*emb[code][d]

__device__ __forceinline__ void cpa16(unsigned dst, const void* src) {
    asm volatile("cp.async.cg.shared.global [%0], [%1], 16;"
                 :: "r"(dst), "l"(src));
}
__device__ __forceinline__ void cpa_commit() {
    asm volatile("cp.async.commit_group;");
}
__device__ __forceinline__ void cpa_wait0() {
    asm volatile("cp.async.wait_group 0;" ::: "memory");
}

// ---------------------------------------------------------------------------
// prep: c2 via 7-register stack fold (== adjacent-pair tree, reference
// numerics) + transposed, pre-doubled codebook for cp.async streaming.
// ---------------------------------------------------------------------------
__global__ void vq_prep(const float* __restrict__ emb) {
    int k = blockIdx.x * 64 + threadIdx.x;    // grid 8 x 64 = 512 codes
    if (k == 0) g_loss = 0.0;
    const int c  = k >> 7;                    // chunk
    const int kk = k & 127;                   // code within chunk
    const float* e = emb + k * DD;
    float st[7];
    int sp = 0;
    #pragma unroll
    for (int d = 0; d < DD; d++) {
        float v = e[d];
        g_ebt[c * (DD * KCH) + d * KCH + kk] = __fadd_rn(v, v);  // exact 2e
        float cur = __fmul_rn(v, v);
        int m = d;
        while (m & 1) { cur = __fadd_rn(st[--sp], cur); m >>= 1; }
        st[sp++] = cur;
    }
    g_c2[k] = st[0];
}

// ---------------------------------------------------------------------------
// main: fused distance GEMM (scalar fp32 FFMA, 8x8 register tile — the r13
// winner) + cp.async double-buffered emb chunks + shfl argmin + fused epilogue.
// es holds 2*e, so acc == fl(2*dot) bit-exactly (RN commutes with x2);
// d = fl( fl(x2+c2) - acc ) reproduces the reference rounding.
// ---------------------------------------------------------------------------
__global__ __launch_bounds__(NTH, 2)
void vq_main(const float* __restrict__ z, const float* __restrict__ emb,
             float* __restrict__ out) {
    extern __shared__ float smem[];
    float* zs   = smem;                       // 64*128
    float* es0  = zs + DD * TILE;             // 64*132
    float* es1  = es0 + DD * ESP;             // 64*132
    float* c2s  = es1 + DD * ESP;             // 512
    float* x2s  = c2s + KKm;                  // 128
    int*   kidx = (int*)(x2s + TILE);         // 128
    float* wred = (float*)(kidx + TILE);      // 8

    const unsigned sbase = (unsigned)__cvta_generic_to_shared(smem);
    const unsigned esb[2] = { sbase + (unsigned)(DD * TILE) * 4u,
                              sbase + (unsigned)(DD * TILE + DD * ESP) * 4u };

    const int tid = threadIdx.x;
    const int tx  = tid & 15;       // code-column group (8 codes)
    const int ty  = tid >> 4;       // token-row group (8 tokens)
    const int tile = blockIdx.x;
    const int b    = tile >> 5;
    const int t0   = (tile & 31) * TILE;
    const size_t zbase = (size_t)b * DD * TTm + t0;

    // ---- kick off chunk-0 emb copy (async), then load z tile + c2 ----
    {
        const char* src = (const char*)(g_ebt);
        #pragma unroll
        for (int j = 0; j < 8; j++) {
            int l = tid + j * NTH;            // 0..2047 16B-lines
            int row = l >> 5, col = l & 31;
            cpa16(esb[0] + (unsigned)(row * ESP * 4 + col * 16),
                  src + row * 512 + col * 16);
        }
        cpa_commit();
    }
    for (int i = tid; i < DD * TILE / 4; i += NTH) {
        int row = i >> 5;
        int col = (i & 31) << 2;
        float4 v = *(const float4*)(z + zbase + (size_t)row * TTm + col);
        *(float4*)(zs + row * TILE + col) = v;
    }
    for (int i = tid; i < KKm; i += NTH) c2s[i] = g_c2[i];
    __syncthreads();                          // zs, c2s visible

    // ---- per-token ||x||^2 (ascending-d fma chain; constant shift of all
    // 512 distances => argmin-order invariant) ----
    if (tid < TILE) {
        float s = 0.f;
        #pragma unroll
        for (int d = 0; d < DD; d++) {
            float v = zs[d * TILE + tid];
            s = fmaf(v, v, s);
        }
        x2s[tid] = s;
    }
    cpa_wait0();
    __syncthreads();                          // es0 + x2s visible

    float bestd[8];
    int   bestk[8];
    #pragma unroll
    for (int i = 0; i < 8; i++) { bestd[i] = FLT_MAX; bestk[i] = 0; }

    #pragma unroll 1
    for (int c = 0; c < KKm / KCH; c++) {
        // stream next chunk into the alternate buffer while computing
        if (c < 3) {
            const char* src = (const char*)(g_ebt + (c + 1) * (DD * KCH));
            unsigned dstb = esb[(c + 1) & 1];
            #pragma unroll
            for (int j = 0; j < 8; j++) {
                int l = tid + j * NTH;
                int row = l >> 5, col = l & 31;
                cpa16(dstb + (unsigned)(row * ESP * 4 + col * 16),
                      src + row * 512 + col * 16);
            }
            cpa_commit();
        }
        const float* es = (c & 1) ? es1 : es0;

        float acc[8][8];
        #pragma unroll
        for (int i = 0; i < 8; i++)
            #pragma unroll
            for (int j = 0; j < 8; j++) acc[i][j] = 0.f;

        // scalar fp32 mainloop: 4x LDS.128 + 64 FFMA per d (r13 pattern)
        #pragma unroll 4
        for (int d = 0; d < DD; d++) {
            float4 a0 = *(const float4*)(zs + d * TILE + ty * 8);
            float4 a1 = *(const float4*)(zs + d * TILE + ty * 8 + 4);
            float4 b0 = *(const float4*)(es + d * ESP + tx * 8);
            float4 b1 = *(const float4*)(es + d * ESP + tx * 8 + 4);
            float av[8] = {a0.x, a0.y, a0.z, a0.w, a1.x, a1.y, a1.z, a1.w};
            float bv[8] = {b0.x, b0.y, b0.z, b0.w, b1.x, b1.y, b1.z, b1.w};
            #pragma unroll
            for (int j = 0; j < 8; j++)
                #pragma unroll
                for (int i = 0; i < 8; i++)
                    acc[i][j] = fmaf(av[i], bv[j], acc[i][j]);
        }

        // chunk epilogue: d = fl( fl(x2+c2) - acc ), acc == fl(2*dot) exactly
        float x2r[8];
        #pragma unroll
        for (int i = 0; i < 8; i++) x2r[i] = x2s[ty * 8 + i];
        #pragma unroll
        for (int j = 0; j < 8; j++) {
            int   kg  = c * KCH + tx * 8 + j;
            float c2v = c2s[kg];
            #pragma unroll
            for (int i = 0; i < 8; i++) {
                float A  = __fadd_rn(x2r[i], c2v);
                float dv = __fsub_rn(A, acc[i][j]);
                bool  lt = dv < bestd[i];
                bestd[i] = lt ? dv : bestd[i];
                bestk[i] = lt ? kg : bestk[i];
            }
        }

        if (c < 3) {
            cpa_wait0();
            __syncthreads();   // next buffer ready; old buffer free
        }
    }

    // ---- cross-tx argmin reduce: 16-lane butterfly shfl, (d,k) lexicographic
    #pragma unroll
    for (int off = 8; off > 0; off >>= 1) {
        #pragma unroll
        for (int i = 0; i < 8; i++) {
            float od = __shfl_xor_sync(0xffffffffu, bestd[i], off);
            int   ok = __shfl_xor_sync(0xffffffffu, bestk[i], off);
            if (od < bestd[i] || (od == bestd[i] && ok < bestk[i])) {
                bestd[i] = od; bestk[i] = ok;
            }
        }
    }
    if (tx == 0) {
        #pragma unroll
        for (int i = 0; i < 8; i++) kidx[ty * 8 + i] = bestk[i];
    }
    __syncthreads();

    // ---- gather + straight-through output + loss (reference rounding) ----
    float lsum = 0.f;
    for (int i = tid; i < DD * TILE; i += NTH) {
        int d = i >> 7;
        int t = i & 127;
        float q  = __ldg(emb + kidx[t] * DD + d);
        float zv = zs[d * TILE + t];
        float diff = __fsub_rn(q, zv);
        out[zbase + (size_t)d * TTm + t] = __fadd_rn(zv, diff);
        lsum = fmaf(diff, diff, lsum);
    }
    #pragma unroll
    for (int o = 16; o > 0; o >>= 1)
        lsum += __shfl_down_sync(0xffffffffu, lsum, o);
    if ((tid & 31) == 0) wred[tid >> 5] = lsum;
    __syncthreads();
    if (tid == 0) {
        float s = 0.f;
        #pragma unroll
        for (int w = 0; w < NW; w++) s += wred[w];
        atomicAdd(&g_loss, (double)s);
        __threadfence();
        unsigned n = atomicAdd(&g_done, 1u);
        if (n == GRID - 1) {
            double m = g_loss / (double)N_ELEM;
            out[N_ELEM]     = (float)m;           // vq_loss
            out[N_ELEM + 1] = (float)(0.25 * m);  // commitment
            g_done = 0;                           // ready for next replay
        }
    }
}

// ---------------------------------------------------------------------------
extern "C" void kernel_launch(void* const* d_in, const int* in_sizes, int n_in,
                              void* d_out, int out_size) {
    const float* z   = (const float*)d_in[0];
    const float* emb = (const float*)d_in[1];
    float*       out = (float*)d_out;

    (void)cudaFuncSetAttribute(vq_main,
                               cudaFuncAttributeMaxDynamicSharedMemorySize,
                               SMEM_BYTES);

    vq_prep<<<8, 64>>>(emb);
    vq_main<<<GRID, NTH, SMEM_BYTES>>>(z, emb, out);
}